// round 1
// baseline (speedup 1.0000x reference)
#include <cuda_runtime.h>

// Problem constants
#define TS   1000
#define BTOT 2048
#define HE   64     // encoder hidden
#define HD   65     // decoder hidden
#define GE   256    // 4*HE
#define GD   260    // 4*HD
#define NB   16     // batch elements per block
#define NTH  256    // threads per block
#define HSTR 72     // h row stride (multiple of 4 floats -> 16B aligned rows)

typedef unsigned long long u64;

__device__ __forceinline__ u64 pack2(float lo, float hi){
    u64 r; asm("mov.b64 %0, {%1, %2};" : "=l"(r) : "f"(lo), "f"(hi)); return r;
}
__device__ __forceinline__ float2 unpk(u64 v){
    float2 f; asm("mov.b64 {%0, %1}, %2;" : "=f"(f.x), "=f"(f.y) : "l"(v)); return f;
}
__device__ __forceinline__ u64 ffma2(u64 a, u64 b, u64 c){
    u64 d; asm("fma.rn.f32x2 %0, %1, %2, %3;" : "=l"(d) : "l"(a), "l"(b), "l"(c)); return d;
}
__device__ __forceinline__ float sigf(float x){
    // accurate enough (~1e-7): ex2-based exp + approx reciprocal
    return __fdividef(1.0f, 1.0f + __expf(-x));
}
__device__ __forceinline__ float tanhf_(float x){
    return fmaf(2.0f, sigf(2.0f * x), -1.0f);
}

__global__ void __launch_bounds__(NTH, 1)
lstm_seq2seq_kernel(const float* __restrict__ input,   // (T,B,1)
                    const float* __restrict__ speed,   // (B,1)
                    const float* __restrict__ target,  // (T,B,1)
                    const float* __restrict__ eWih,    // (256,1)
                    const float* __restrict__ eWhh,    // (256,64)
                    const float* __restrict__ ebih,    // (256)
                    const float* __restrict__ ebhh,    // (256)
                    const float* __restrict__ dWih,    // (260,1)
                    const float* __restrict__ dWhh,    // (260,65)
                    const float* __restrict__ dbih,    // (260)
                    const float* __restrict__ dbhh,    // (260)
                    const float* __restrict__ linW,    // (1,65)
                    const float* __restrict__ linb,    // (1)
                    const float* __restrict__ denW,    // (1,1)
                    const float* __restrict__ denb,    // (1)
                    float* __restrict__ out)           // (T,B,1)
{
    __shared__ __align__(16) float h_s[NB][HSTR];   // hidden state per batch
    __shared__ __align__(16) float g_s[NB][GD];     // gates (also reused as c scratch at transition)
    __shared__ float x_s[2][NB];                    // double-buffered scalar inputs
    __shared__ __align__(16) float wx_s[4][HSTR];   // decoder leftover rows 256..259
    __shared__ float wih_x[4], b_x[4];
    __shared__ float lw_s[HD];
    __shared__ float sp_s[NB];

    const int tid = threadIdx.x;
    const int b0  = blockIdx.x * NB;

    // ---------------- encoder weight load: row `tid` of Whh into registers ----------------
    u64 wp[32];          // 64 weights as 32 packed f32x2 pairs
    {
        const ulonglong2* wr = (const ulonglong2*)(eWhh + tid * HE);
        #pragma unroll
        for (int j = 0; j < 16; j++){ ulonglong2 v = wr[j]; wp[2*j] = v.x; wp[2*j+1] = v.y; }
    }
    float wih  = eWih[tid];
    float bias = ebih[tid] + ebhh[tid];

    // zero hidden state
    for (int i = tid; i < NB * HSTR; i += NTH) ((float*)h_s)[i] = 0.0f;

    // encoder activation item mapping: thread owns (b = eb+4j, u = eu), j=0..3, c in regs
    const int eu = tid & 63;
    const int eb = tid >> 6;
    float c0 = 0.f, c1 = 0.f, c2 = 0.f, c3 = 0.f;

    if (tid < NB) x_s[0][tid] = input[b0 + tid];
    __syncthreads();

    // ================= encoder recurrence =================
    for (int t = 0; t < TS; t++){
        const float* xr = x_s[t & 1];
        float xnext = 0.0f;
        if (tid < NB && t + 1 < TS) xnext = input[(t + 1) * BTOT + b0 + tid];

        // GEMM phase: gates[b][tid] = Whh[tid,:] . h[b,:] + wih*x[b] + bias
        #pragma unroll 2
        for (int b = 0; b < NB; b++){
            const ulonglong2* hp = (const ulonglong2*)h_s[b];
            u64 a0 = 0ull, a1 = 0ull;
            #pragma unroll
            for (int j = 0; j < 16; j++){
                ulonglong2 hv = hp[j];
                a0 = ffma2(hv.x, wp[2*j],     a0);
                a1 = ffma2(hv.y, wp[2*j + 1], a1);
            }
            float2 p = unpk(a0), q = unpk(a1);
            g_s[b][tid] = (p.x + p.y) + (q.x + q.y) + fmaf(wih, xr[b], bias);
        }
        __syncthreads();

        // activation phase (PyTorch gate order i,f,g,o)
        {
            int bb;
            float ig, fg, gg, og, cc;
            bb = eb;      ig = g_s[bb][eu]; fg = g_s[bb][HE+eu]; gg = g_s[bb][2*HE+eu]; og = g_s[bb][3*HE+eu];
            cc = sigf(fg)*c0 + sigf(ig)*tanhf_(gg); c0 = cc; h_s[bb][eu] = sigf(og)*tanhf_(cc);
            bb = eb + 4;  ig = g_s[bb][eu]; fg = g_s[bb][HE+eu]; gg = g_s[bb][2*HE+eu]; og = g_s[bb][3*HE+eu];
            cc = sigf(fg)*c1 + sigf(ig)*tanhf_(gg); c1 = cc; h_s[bb][eu] = sigf(og)*tanhf_(cc);
            bb = eb + 8;  ig = g_s[bb][eu]; fg = g_s[bb][HE+eu]; gg = g_s[bb][2*HE+eu]; og = g_s[bb][3*HE+eu];
            cc = sigf(fg)*c2 + sigf(ig)*tanhf_(gg); c2 = cc; h_s[bb][eu] = sigf(og)*tanhf_(cc);
            bb = eb + 12; ig = g_s[bb][eu]; fg = g_s[bb][HE+eu]; gg = g_s[bb][2*HE+eu]; og = g_s[bb][3*HE+eu];
            cc = sigf(fg)*c3 + sigf(ig)*tanhf_(gg); c3 = cc; h_s[bb][eu] = sigf(og)*tanhf_(cc);
        }
        if (tid < NB) x_s[(t + 1) & 1][tid] = xnext;
        __syncthreads();
    }

    // ================= encoder -> decoder transition =================
    // park encoder c in g_s (same (b,u) layout)
    g_s[eb     ][eu] = c0;
    g_s[eb + 4 ][eu] = c1;
    g_s[eb + 8 ][eu] = c2;
    g_s[eb + 12][eu] = c3;

    if (tid < NB){
        float sp = fmaf(speed[b0 + tid], denW[0], denb[0]);
        sp_s[tid]     = sp;
        h_s[tid][HE]  = sp;     // 65th hidden element
        x_s[0][tid]   = 0.0f;   // teacher forcing: x_dec[0] = 0
    }
    if (tid < HD) lw_s[tid] = linW[tid];

    // decoder main-row weights (row tid, 65 wide) into registers
    float wlast;
    {
        const float* wr = dWhh + tid * HD;
        #pragma unroll
        for (int j = 0; j < 32; j++) wp[j] = pack2(wr[2*j], wr[2*j+1]);
        wlast = wr[64];
    }
    wih  = dWih[tid];
    bias = dbih[tid] + dbhh[tid];

    // leftover rows 256..259 -> shared
    if (tid < 4){
        const float* wr = dWhh + (GE + tid) * HD;
        for (int k = 0; k < HD; k++) wx_s[tid][k] = wr[k];
        wih_x[tid] = dWih[GE + tid];
        b_x[tid]   = dbih[GE + tid] + dbhh[GE + tid];
    }
    __syncthreads();

    // decoder activation items: flat n = tid + 256*j over NB*HD = 1040 items
    int   db[5], du[5];
    float dc[5];
    #pragma unroll
    for (int j = 0; j < 5; j++){
        int n = tid + NTH * j;
        bool v = (n < NB * HD);
        int bb = v ? (n / HD) : 0;
        int uu = v ? (n - bb * HD) : 0;
        db[j] = bb; du[j] = uu;
        dc[j] = v ? ((uu < HE) ? g_s[bb][uu] : sp_s[bb]) : 0.0f;
    }
    float lb = linb[0];
    __syncthreads();   // all c-init reads of g_s done before GEMM overwrites it

    // ================= decoder recurrence =================
    for (int t = 0; t < TS; t++){
        const float* xr = x_s[t & 1];

        // output projection for previous step's h (h_s stable during GEMM phase)
        if (tid < NB && t > 0){
            float acc = lb;
            #pragma unroll
            for (int k = 0; k < HD; k++) acc = fmaf(lw_s[k], h_s[tid][k], acc);
            out[(t - 1) * BTOT + b0 + tid] = acc;
        }

        float xnext = 0.0f;
        if (tid < NB && t < TS - 1) xnext = target[t * BTOT + b0 + tid]; // x_dec[t+1] = target[t]

        // GEMM phase: main rows 0..255
        #pragma unroll 2
        for (int b = 0; b < NB; b++){
            const ulonglong2* hp = (const ulonglong2*)h_s[b];
            u64 a0 = 0ull, a1 = 0ull;
            #pragma unroll
            for (int j = 0; j < 16; j++){
                ulonglong2 hv = hp[j];
                a0 = ffma2(hv.x, wp[2*j],     a0);
                a1 = ffma2(hv.y, wp[2*j + 1], a1);
            }
            float2 p = unpk(a0), q = unpk(a1);
            g_s[b][tid] = (p.x + p.y) + (q.x + q.y)
                        + fmaf(wlast, h_s[b][HE], fmaf(wih, xr[b], bias));
        }
        // leftover rows 256..259: thread tid<64 does (row 256+(tid&3), batch tid>>2)
        if (tid < 64){
            int r = tid & 3, bb = tid >> 2;
            float acc = fmaf(wih_x[r], xr[bb], b_x[r]);
            #pragma unroll
            for (int k = 0; k < HD; k++) acc = fmaf(wx_s[r][k], h_s[bb][k], acc);
            g_s[bb][GE + r] = acc;
        }
        __syncthreads();

        // activation phase, H = 65
        #pragma unroll
        for (int j = 0; j < 5; j++){
            if (j < 4 || tid < NB){
                int bb = db[j], uu = du[j];
                float ig = g_s[bb][uu];
                float fg = g_s[bb][HD + uu];
                float gg = g_s[bb][2*HD + uu];
                float og = g_s[bb][3*HD + uu];
                float cc = sigf(fg) * dc[j] + sigf(ig) * tanhf_(gg);
                dc[j] = cc;
                h_s[bb][uu] = sigf(og) * tanhf_(cc);
            }
        }
        if (tid < NB) x_s[(t + 1) & 1][tid] = xnext;
        __syncthreads();
    }

    // final output (t = TS-1)
    if (tid < NB){
        float acc = lb;
        #pragma unroll
        for (int k = 0; k < HD; k++) acc = fmaf(lw_s[k], h_s[tid][k], acc);
        out[(TS - 1) * BTOT + b0 + tid] = acc;
    }
}

extern "C" void kernel_launch(void* const* d_in, const int* in_sizes, int n_in,
                              void* d_out, int out_size)
{
    const float* input  = (const float*)d_in[0];
    const float* speed  = (const float*)d_in[1];
    const float* target = (const float*)d_in[2];
    const float* eWih   = (const float*)d_in[3];
    const float* eWhh   = (const float*)d_in[4];
    const float* ebih   = (const float*)d_in[5];
    const float* ebhh   = (const float*)d_in[6];
    const float* dWih   = (const float*)d_in[7];
    const float* dWhh   = (const float*)d_in[8];
    const float* dbih   = (const float*)d_in[9];
    const float* dbhh   = (const float*)d_in[10];
    const float* linW   = (const float*)d_in[11];
    const float* linb   = (const float*)d_in[12];
    const float* denW   = (const float*)d_in[13];
    const float* denb   = (const float*)d_in[14];
    float* outp = (float*)d_out;

    dim3 grid(BTOT / NB);   // 128 blocks
    dim3 block(NTH);        // 256 threads
    lstm_seq2seq_kernel<<<grid, block>>>(input, speed, target,
                                         eWih, eWhh, ebih, ebhh,
                                         dWih, dWhh, dbih, dbhh,
                                         linW, linb, denW, denb, outp);
}

// round 2
// speedup vs baseline: 1.0997x; 1.0997x over previous
#include <cuda_runtime.h>

// Problem constants
#define TS   1000
#define BTOT 2048
#define HE   64     // encoder hidden
#define HD   65     // decoder hidden
#define GE   256    // 4*HE
#define GD   260    // 4*HD
#define NB   16     // batch elements per block
#define NTH  512    // threads per block
#define HSTR 72     // h row stride (multiple of 4 floats -> 16B aligned rows)

typedef unsigned long long u64;

__device__ __forceinline__ u64 pack2(float lo, float hi){
    u64 r; asm("mov.b64 %0, {%1, %2};" : "=l"(r) : "f"(lo), "f"(hi)); return r;
}
__device__ __forceinline__ float2 unpk(u64 v){
    float2 f; asm("mov.b64 {%0, %1}, %2;" : "=f"(f.x), "=f"(f.y) : "l"(v)); return f;
}
__device__ __forceinline__ u64 ffma2(u64 a, u64 b, u64 c){
    u64 d; asm("fma.rn.f32x2 %0, %1, %2, %3;" : "=l"(d) : "l"(a), "l"(b), "l"(c)); return d;
}
__device__ __forceinline__ float sigf(float x){
    return __fdividef(1.0f, 1.0f + __expf(-x));
}
__device__ __forceinline__ float tanhf_(float x){
    return fmaf(2.0f, sigf(2.0f * x), -1.0f);
}

__global__ void __launch_bounds__(NTH, 1)
lstm_seq2seq_kernel(const float* __restrict__ input,   // (T,B,1)
                    const float* __restrict__ speed,   // (B,1)
                    const float* __restrict__ target,  // (T,B,1)
                    const float* __restrict__ eWih,    // (256,1)
                    const float* __restrict__ eWhh,    // (256,64)
                    const float* __restrict__ ebih,    // (256)
                    const float* __restrict__ ebhh,    // (256)
                    const float* __restrict__ dWih,    // (260,1)
                    const float* __restrict__ dWhh,    // (260,65)
                    const float* __restrict__ dbih,    // (260)
                    const float* __restrict__ dbhh,    // (260)
                    const float* __restrict__ linW,    // (1,65)
                    const float* __restrict__ linb,    // (1)
                    const float* __restrict__ denW,    // (1,1)
                    const float* __restrict__ denb,    // (1)
                    float* __restrict__ out)           // (T,B,1)
{
    __shared__ __align__(16) float h_s[NB][HSTR];   // hidden state per batch
    __shared__ __align__(16) float g_s[NB][GD];     // gates (reused as c scratch at transition)
    __shared__ float x_s[2][NB];                    // double-buffered scalar inputs
    __shared__ __align__(16) float wx_s[4][HSTR];   // decoder leftover rows 256..259
    __shared__ float wih_x[4], b_x[4];
    __shared__ float lw_s[HD];
    __shared__ float sp_s[NB];

    const int tid = threadIdx.x;
    const int b0  = blockIdx.x * NB;

    // thread -> (gate row r, batch half)
    const int r     = tid & 255;       // gate row 0..255
    const int half  = tid >> 8;        // 0 or 1
    const int bbase = half * 8;        // batches bbase..bbase+7

    // ---------------- encoder weights: row r of Whh into registers ----------------
    u64 wp[32];          // 64 weights as 32 packed f32x2 pairs
    {
        const ulonglong2* wr = (const ulonglong2*)(eWhh + r * HE);
        #pragma unroll
        for (int j = 0; j < 16; j++){ ulonglong2 v = wr[j]; wp[2*j] = v.x; wp[2*j+1] = v.y; }
    }
    float wih  = eWih[r];
    float bias = ebih[r] + ebhh[r];

    // zero hidden state
    for (int i = tid; i < NB * HSTR; i += NTH) ((float*)h_s)[i] = 0.0f;

    // encoder activation mapping: thread owns unit eu of batches eb and eb+8
    const int eu = tid & 63;
    const int eb = tid >> 6;           // 0..7
    float c0 = 0.f, c1 = 0.f;

    if (tid < NB) x_s[0][tid] = input[b0 + tid];
    __syncthreads();

    // ================= encoder recurrence =================
    for (int t = 0; t < TS; t++){
        const float* xr = x_s[t & 1];
        float xnext = 0.0f;
        if (tid < NB && t + 1 < TS) xnext = input[(t + 1) * BTOT + b0 + tid];

        // GEMM phase: gates[bb][r] = Whh[r,:] . h[bb,:] + wih*x[bb] + bias
        #pragma unroll 2
        for (int b = 0; b < 8; b++){
            const int bb = bbase + b;
            const ulonglong2* hp = (const ulonglong2*)h_s[bb];
            u64 a0 = 0ull, a1 = 0ull;
            #pragma unroll
            for (int j = 0; j < 16; j++){
                ulonglong2 hv = hp[j];
                a0 = ffma2(hv.x, wp[2*j],     a0);
                a1 = ffma2(hv.y, wp[2*j + 1], a1);
            }
            float2 p = unpk(a0), q = unpk(a1);
            g_s[bb][r] = (p.x + p.y) + (q.x + q.y) + fmaf(wih, xr[bb], bias);
        }
        __syncthreads();

        // activation phase (PyTorch gate order i,f,g,o), 2 items per thread
        {
            int bb; float ig, fg, gg, og, cc;
            bb = eb;     ig = g_s[bb][eu]; fg = g_s[bb][HE+eu]; gg = g_s[bb][2*HE+eu]; og = g_s[bb][3*HE+eu];
            cc = sigf(fg)*c0 + sigf(ig)*tanhf_(gg); c0 = cc; h_s[bb][eu] = sigf(og)*tanhf_(cc);
            bb = eb + 8; ig = g_s[bb][eu]; fg = g_s[bb][HE+eu]; gg = g_s[bb][2*HE+eu]; og = g_s[bb][3*HE+eu];
            cc = sigf(fg)*c1 + sigf(ig)*tanhf_(gg); c1 = cc; h_s[bb][eu] = sigf(og)*tanhf_(cc);
        }
        if (tid < NB) x_s[(t + 1) & 1][tid] = xnext;
        __syncthreads();
    }

    // ================= encoder -> decoder transition =================
    // park encoder c in g_s (same (b,u) layout)
    g_s[eb    ][eu] = c0;
    g_s[eb + 8][eu] = c1;

    if (tid < NB){
        float sp = fmaf(speed[b0 + tid], denW[0], denb[0]);
        sp_s[tid]     = sp;
        h_s[tid][HE]  = sp;     // 65th hidden element
        x_s[0][tid]   = 0.0f;   // teacher forcing: x_dec[0] = 0
    }
    if (tid < HD) lw_s[tid] = linW[tid];

    // decoder main-row weights (row r, 65 wide) into registers
    float wlast;
    {
        const float* wr = dWhh + r * HD;
        #pragma unroll
        for (int j = 0; j < 32; j++) wp[j] = pack2(wr[2*j], wr[2*j+1]);
        wlast = wr[64];
    }
    wih  = dWih[r];
    bias = dbih[r] + dbhh[r];

    // leftover rows 256..259 -> shared
    if (tid < 4){
        const float* wr = dWhh + (GE + tid) * HD;
        for (int k = 0; k < HD; k++) wx_s[tid][k] = wr[k];
        wih_x[tid] = dWih[GE + tid];
        b_x[tid]   = dbih[GE + tid] + dbhh[GE + tid];
    }
    __syncthreads();

    // decoder activation items: flat n = tid + 512*j over NB*HD = 1040 items
    int   db[3], du[3];
    float dc[3];
    #pragma unroll
    for (int j = 0; j < 3; j++){
        int n = tid + NTH * j;
        bool v = (n < NB * HD);
        int bb = v ? (n / HD) : 0;
        int uu = v ? (n - bb * HD) : 0;
        db[j] = bb; du[j] = uu;
        dc[j] = v ? ((uu < HE) ? g_s[bb][uu] : sp_s[bb]) : 0.0f;
    }
    float lb = linb[0];
    __syncthreads();   // all c-init reads of g_s done before GEMM overwrites it

    // ================= decoder recurrence =================
    for (int t = 0; t < TS; t++){
        const float* xr = x_s[t & 1];

        // output projection for previous step's h (h_s stable during GEMM phase)
        if (tid < NB && t > 0){
            float a0 = lb, a1 = 0.f, a2 = 0.f, a3 = 0.f;
            #pragma unroll
            for (int k = 0; k < 64; k += 4){
                a0 = fmaf(lw_s[k  ], h_s[tid][k  ], a0);
                a1 = fmaf(lw_s[k+1], h_s[tid][k+1], a1);
                a2 = fmaf(lw_s[k+2], h_s[tid][k+2], a2);
                a3 = fmaf(lw_s[k+3], h_s[tid][k+3], a3);
            }
            a0 = fmaf(lw_s[64], h_s[tid][64], a0);
            out[(t - 1) * BTOT + b0 + tid] = (a0 + a1) + (a2 + a3);
        }

        float xnext = 0.0f;
        if (tid < NB && t < TS - 1) xnext = target[t * BTOT + b0 + tid]; // x_dec[t+1] = target[t]

        // GEMM phase: main rows 0..255, batches bbase..bbase+7
        #pragma unroll 2
        for (int b = 0; b < 8; b++){
            const int bb = bbase + b;
            const ulonglong2* hp = (const ulonglong2*)h_s[bb];
            u64 a0 = 0ull, a1 = 0ull;
            #pragma unroll
            for (int j = 0; j < 16; j++){
                ulonglong2 hv = hp[j];
                a0 = ffma2(hv.x, wp[2*j],     a0);
                a1 = ffma2(hv.y, wp[2*j + 1], a1);
            }
            float2 p = unpk(a0), q = unpk(a1);
            g_s[bb][r] = (p.x + p.y) + (q.x + q.y)
                       + fmaf(wlast, h_s[bb][HE], fmaf(wih, xr[bb], bias));
        }
        // leftover rows 256..259: last 2 warps, item idx = (row 256+(i&3), batch i>>2)
        if (tid >= NTH - 64){
            int i = tid - (NTH - 64);
            int rr = i & 3, bb = i >> 2;
            float acc = fmaf(wih_x[rr], xr[bb], b_x[rr]);
            #pragma unroll
            for (int k = 0; k < HD; k++) acc = fmaf(wx_s[rr][k], h_s[bb][k], acc);
            g_s[bb][GE + rr] = acc;
        }
        __syncthreads();

        // activation phase, H = 65
        #pragma unroll
        for (int j = 0; j < 3; j++){
            if (j < 2 || tid < NB){
                int bb = db[j], uu = du[j];
                float ig = g_s[bb][uu];
                float fg = g_s[bb][HD + uu];
                float gg = g_s[bb][2*HD + uu];
                float og = g_s[bb][3*HD + uu];
                float cc = sigf(fg) * dc[j] + sigf(ig) * tanhf_(gg);
                dc[j] = cc;
                h_s[bb][uu] = sigf(og) * tanhf_(cc);
            }
        }
        if (tid < NB) x_s[(t + 1) & 1][tid] = xnext;
        __syncthreads();
    }

    // final output (t = TS-1)
    if (tid < NB){
        float a0 = lb, a1 = 0.f, a2 = 0.f, a3 = 0.f;
        #pragma unroll
        for (int k = 0; k < 64; k += 4){
            a0 = fmaf(lw_s[k  ], h_s[tid][k  ], a0);
            a1 = fmaf(lw_s[k+1], h_s[tid][k+1], a1);
            a2 = fmaf(lw_s[k+2], h_s[tid][k+2], a2);
            a3 = fmaf(lw_s[k+3], h_s[tid][k+3], a3);
        }
        a0 = fmaf(lw_s[64], h_s[tid][64], a0);
        out[(TS - 1) * BTOT + b0 + tid] = (a0 + a1) + (a2 + a3);
    }
}

extern "C" void kernel_launch(void* const* d_in, const int* in_sizes, int n_in,
                              void* d_out, int out_size)
{
    const float* input  = (const float*)d_in[0];
    const float* speed  = (const float*)d_in[1];
    const float* target = (const float*)d_in[2];
    const float* eWih   = (const float*)d_in[3];
    const float* eWhh   = (const float*)d_in[4];
    const float* ebih   = (const float*)d_in[5];
    const float* ebhh   = (const float*)d_in[6];
    const float* dWih   = (const float*)d_in[7];
    const float* dWhh   = (const float*)d_in[8];
    const float* dbih   = (const float*)d_in[9];
    const float* dbhh   = (const float*)d_in[10];
    const float* linW   = (const float*)d_in[11];
    const float* linb   = (const float*)d_in[12];
    const float* denW   = (const float*)d_in[13];
    const float* denb   = (const float*)d_in[14];
    float* outp = (float*)d_out;

    dim3 grid(BTOT / NB);   // 128 blocks
    dim3 block(NTH);        // 512 threads
    lstm_seq2seq_kernel<<<grid, block>>>(input, speed, target,
                                         eWih, eWhh, ebih, ebhh,
                                         dWih, dWhh, dbih, dbhh,
                                         linW, linb, denW, denb, outp);
}

// round 3
// speedup vs baseline: 1.1584x; 1.0534x over previous
#include <cuda_runtime.h>

// Problem constants
#define TS   1000
#define BTOT 2048
#define HE   64     // encoder hidden
#define HD   65     // decoder hidden
#define GE   256    // 4*HE
#define GD   260    // 4*HD
#define NB   8      // batch elements per block
#define NTH  256    // threads per block
#define HSTR 68     // h row stride (68*4=272B, 16B-aligned rows, conflict-free col reads)

typedef unsigned long long u64;

__device__ __forceinline__ u64 pack2(float lo, float hi){
    u64 r; asm("mov.b64 %0, {%1, %2};" : "=l"(r) : "f"(lo), "f"(hi)); return r;
}
__device__ __forceinline__ float2 unpk(u64 v){
    float2 f; asm("mov.b64 {%0, %1}, %2;" : "=f"(f.x), "=f"(f.y) : "l"(v)); return f;
}
__device__ __forceinline__ u64 ffma2(u64 a, u64 b, u64 c){
    u64 d; asm("fma.rn.f32x2 %0, %1, %2, %3;" : "=l"(d) : "l"(a), "l"(b), "l"(c)); return d;
}
__device__ __forceinline__ float sigf(float x){
    return __fdividef(1.0f, 1.0f + __expf(-x));
}
__device__ __forceinline__ float tanhf_(float x){
    return fmaf(2.0f, sigf(2.0f * x), -1.0f);
}

__global__ void __launch_bounds__(NTH, 2)
lstm_seq2seq_kernel(const float* __restrict__ input,   // (T,B,1)
                    const float* __restrict__ speed,   // (B,1)
                    const float* __restrict__ target,  // (T,B,1)
                    const float* __restrict__ eWih,    // (256,1)
                    const float* __restrict__ eWhh,    // (256,64)
                    const float* __restrict__ ebih,    // (256)
                    const float* __restrict__ ebhh,    // (256)
                    const float* __restrict__ dWih,    // (260,1)
                    const float* __restrict__ dWhh,    // (260,65)
                    const float* __restrict__ dbih,    // (260)
                    const float* __restrict__ dbhh,    // (260)
                    const float* __restrict__ linW,    // (1,65)
                    const float* __restrict__ linb,    // (1)
                    const float* __restrict__ denW,    // (1,1)
                    const float* __restrict__ denb,    // (1)
                    float* __restrict__ out)           // (T,B,1)
{
    __shared__ __align__(16) float h_s[NB][HSTR];   // hidden state per batch
    __shared__ __align__(16) float g_s[NB][GD];     // gates (reused as c scratch at transition)
    __shared__ float x_s[2][NB];                    // double-buffered scalar inputs
    __shared__ __align__(16) float wx_s[4][HSTR];   // decoder leftover rows 256..259
    __shared__ float wih_x[4], b_x[4];
    __shared__ float lw_s[HD];
    __shared__ float sp_s[NB];

    const int tid = threadIdx.x;
    const int b0  = blockIdx.x * NB;
    const int r   = tid;               // gate row 0..255

    // ---------------- encoder weights: row r of Whh into registers ----------------
    u64 wp[32];          // 64 weights as 32 packed f32x2 pairs
    {
        const ulonglong2* wr = (const ulonglong2*)(eWhh + r * HE);
        #pragma unroll
        for (int j = 0; j < 16; j++){ ulonglong2 v = wr[j]; wp[2*j] = v.x; wp[2*j+1] = v.y; }
    }
    float wih  = eWih[r];
    float bias = ebih[r] + ebhh[r];

    // zero hidden state
    for (int i = tid; i < NB * HSTR; i += NTH) ((float*)h_s)[i] = 0.0f;

    // encoder activation mapping: thread owns unit eu of batches eb and eb+4
    const int eu = tid & 63;
    const int eb = tid >> 6;           // 0..3
    float c0 = 0.f, c1 = 0.f;

    if (tid < NB) x_s[0][tid] = input[b0 + tid];
    __syncthreads();

    // ================= encoder recurrence =================
    for (int t = 0; t < TS; t++){
        const float* xr = x_s[t & 1];
        float xnext = 0.0f;
        if (tid < NB && t + 1 < TS) xnext = input[(t + 1) * BTOT + b0 + tid];

        // GEMM phase: gates[bb][r] = Whh[r,:] . h[bb,:] + wih*x[bb] + bias
        #pragma unroll 2
        for (int bb = 0; bb < NB; bb++){
            const ulonglong2* hp = (const ulonglong2*)h_s[bb];
            u64 a0 = 0ull, a1 = 0ull;
            #pragma unroll
            for (int j = 0; j < 16; j++){
                ulonglong2 hv = hp[j];
                a0 = ffma2(hv.x, wp[2*j],     a0);
                a1 = ffma2(hv.y, wp[2*j + 1], a1);
            }
            float2 p = unpk(a0), q = unpk(a1);
            g_s[bb][r] = (p.x + p.y) + (q.x + q.y) + fmaf(wih, xr[bb], bias);
        }
        __syncthreads();

        // activation phase (PyTorch gate order i,f,g,o), 2 items per thread
        {
            int bb; float ig, fg, gg, og, cc;
            bb = eb;     ig = g_s[bb][eu]; fg = g_s[bb][HE+eu]; gg = g_s[bb][2*HE+eu]; og = g_s[bb][3*HE+eu];
            cc = sigf(fg)*c0 + sigf(ig)*tanhf_(gg); c0 = cc; h_s[bb][eu] = sigf(og)*tanhf_(cc);
            bb = eb + 4; ig = g_s[bb][eu]; fg = g_s[bb][HE+eu]; gg = g_s[bb][2*HE+eu]; og = g_s[bb][3*HE+eu];
            cc = sigf(fg)*c1 + sigf(ig)*tanhf_(gg); c1 = cc; h_s[bb][eu] = sigf(og)*tanhf_(cc);
        }
        if (tid < NB) x_s[(t + 1) & 1][tid] = xnext;
        __syncthreads();
    }

    // ================= encoder -> decoder transition =================
    // park encoder c in g_s (same (b,u) layout)
    g_s[eb    ][eu] = c0;
    g_s[eb + 4][eu] = c1;

    if (tid < NB){
        float sp = fmaf(speed[b0 + tid], denW[0], denb[0]);
        sp_s[tid]     = sp;
        h_s[tid][HE]  = sp;     // 65th hidden element
        x_s[0][tid]   = 0.0f;   // teacher forcing: x_dec[0] = 0
    }
    if (tid < HD) lw_s[tid] = linW[tid];

    // decoder main-row weights (row r, 65 wide) into registers
    float wlast;
    {
        const float* wr = dWhh + r * HD;
        #pragma unroll
        for (int j = 0; j < 32; j++) wp[j] = pack2(wr[2*j], wr[2*j+1]);
        wlast = wr[64];
    }
    wih  = dWih[r];
    bias = dbih[r] + dbhh[r];

    // leftover rows 256..259 -> shared
    if (tid < 4){
        const float* wr = dWhh + (GE + tid) * HD;
        for (int k = 0; k < HD; k++) wx_s[tid][k] = wr[k];
        wih_x[tid] = dWih[GE + tid];
        b_x[tid]   = dbih[GE + tid] + dbhh[GE + tid];
    }
    __syncthreads();

    // decoder activation items: flat n = tid + 256*j over NB*HD = 520 items
    int   db[3], du[3];
    float dc[3];
    #pragma unroll
    for (int j = 0; j < 3; j++){
        int n = tid + NTH * j;
        bool v = (n < NB * HD);
        int bb = v ? (n / HD) : 0;
        int uu = v ? (n - bb * HD) : 0;
        db[j] = bb; du[j] = uu;
        dc[j] = v ? ((uu < HE) ? g_s[bb][uu] : sp_s[bb]) : 0.0f;
    }
    float lb = linb[0];
    __syncthreads();   // all c-init reads of g_s done before GEMM overwrites it

    // ================= decoder recurrence =================
    for (int t = 0; t < TS; t++){
        const float* xr = x_s[t & 1];

        // output projection for previous step's h (h_s stable during GEMM phase)
        if (tid < NB && t > 0){
            float a0 = lb, a1 = 0.f, a2 = 0.f, a3 = 0.f;
            #pragma unroll
            for (int k = 0; k < 64; k += 4){
                a0 = fmaf(lw_s[k  ], h_s[tid][k  ], a0);
                a1 = fmaf(lw_s[k+1], h_s[tid][k+1], a1);
                a2 = fmaf(lw_s[k+2], h_s[tid][k+2], a2);
                a3 = fmaf(lw_s[k+3], h_s[tid][k+3], a3);
            }
            a0 = fmaf(lw_s[64], h_s[tid][64], a0);
            out[(t - 1) * BTOT + b0 + tid] = (a0 + a1) + (a2 + a3);
        }

        float xnext = 0.0f;
        if (tid < NB && t < TS - 1) xnext = target[t * BTOT + b0 + tid]; // x_dec[t+1] = target[t]

        // GEMM phase: main rows 0..255, all NB batches
        #pragma unroll 2
        for (int bb = 0; bb < NB; bb++){
            const ulonglong2* hp = (const ulonglong2*)h_s[bb];
            u64 a0 = 0ull, a1 = 0ull;
            #pragma unroll
            for (int j = 0; j < 16; j++){
                ulonglong2 hv = hp[j];
                a0 = ffma2(hv.x, wp[2*j],     a0);
                a1 = ffma2(hv.y, wp[2*j + 1], a1);
            }
            float2 p = unpk(a0), q = unpk(a1);
            g_s[bb][r] = (p.x + p.y) + (q.x + q.y)
                       + fmaf(wlast, h_s[bb][HE], fmaf(wih, xr[bb], bias));
        }
        // leftover rows 256..259: last warp, item i = (row 256+(i&3), batch i>>2)
        if (tid >= NTH - 32){
            int i = tid - (NTH - 32);
            int rr = i & 3, bb = i >> 2;
            float acc = fmaf(wih_x[rr], xr[bb], b_x[rr]);
            #pragma unroll
            for (int k = 0; k < HD; k++) acc = fmaf(wx_s[rr][k], h_s[bb][k], acc);
            g_s[bb][GE + rr] = acc;
        }
        __syncthreads();

        // activation phase, H = 65
        #pragma unroll
        for (int j = 0; j < 3; j++){
            if (j < 2 || tid < NB * HD - 2 * NTH){
                int bb = db[j], uu = du[j];
                float ig = g_s[bb][uu];
                float fg = g_s[bb][HD + uu];
                float gg = g_s[bb][2*HD + uu];
                float og = g_s[bb][3*HD + uu];
                float cc = sigf(fg) * dc[j] + sigf(ig) * tanhf_(gg);
                dc[j] = cc;
                h_s[bb][uu] = sigf(og) * tanhf_(cc);
            }
        }
        if (tid < NB) x_s[(t + 1) & 1][tid] = xnext;
        __syncthreads();
    }

    // final output (t = TS-1)
    if (tid < NB){
        float a0 = lb, a1 = 0.f, a2 = 0.f, a3 = 0.f;
        #pragma unroll
        for (int k = 0; k < 64; k += 4){
            a0 = fmaf(lw_s[k  ], h_s[tid][k  ], a0);
            a1 = fmaf(lw_s[k+1], h_s[tid][k+1], a1);
            a2 = fmaf(lw_s[k+2], h_s[tid][k+2], a2);
            a3 = fmaf(lw_s[k+3], h_s[tid][k+3], a3);
        }
        a0 = fmaf(lw_s[64], h_s[tid][64], a0);
        out[(TS - 1) * BTOT + b0 + tid] = (a0 + a1) + (a2 + a3);
    }
}

extern "C" void kernel_launch(void* const* d_in, const int* in_sizes, int n_in,
                              void* d_out, int out_size)
{
    const float* input  = (const float*)d_in[0];
    const float* speed  = (const float*)d_in[1];
    const float* target = (const float*)d_in[2];
    const float* eWih   = (const float*)d_in[3];
    const float* eWhh   = (const float*)d_in[4];
    const float* ebih   = (const float*)d_in[5];
    const float* ebhh   = (const float*)d_in[6];
    const float* dWih   = (const float*)d_in[7];
    const float* dWhh   = (const float*)d_in[8];
    const float* dbih   = (const float*)d_in[9];
    const float* dbhh   = (const float*)d_in[10];
    const float* linW   = (const float*)d_in[11];
    const float* linb   = (const float*)d_in[12];
    const float* denW   = (const float*)d_in[13];
    const float* denb   = (const float*)d_in[14];
    float* outp = (float*)d_out;

    dim3 grid(BTOT / NB);   // 256 blocks -> 2 CTAs/SM co-resident
    dim3 block(NTH);        // 256 threads
    lstm_seq2seq_kernel<<<grid, block>>>(input, speed, target,
                                         eWih, eWhh, ebih, ebhh,
                                         dWih, dWhh, dbih, dbhh,
                                         linW, linb, denW, denb, outp);
}